// round 2
// baseline (speedup 1.0000x reference)
#include <cuda_runtime.h>

// x: [8, 256, 16, 56, 56] fp32, weight: [256, 1, 3] fp32
// y[n,c,t,h,w] = w[c,0]*x[t-2] + w[c,1]*x[t] + w[c,2]*x[t+2] (zero outside t)
//
// HW = 3136 floats contiguous per (n,c,t) plane; T=16; NC=2048.
// One thread owns TWO hw4-chunks (q and q+392) of a full t-line:
// each input element read exactly once, each output written once.
// Two independent rolling windows double per-thread MLP.

__global__ __launch_bounds__(256) void tshift_kernel(
    const float* __restrict__ x,
    const float* __restrict__ w,
    float* __restrict__ y)
{
    constexpr int HW4  = 3136 / 4;   // 784 float4 per plane
    constexpr int HALF = HW4 / 2;    // 392
    constexpr int T    = 16;
    constexpr int THW  = T * 3136;   // floats per (n,c) line

    int idx = blockIdx.x * blockDim.x + threadIdx.x;   // 0 .. 2048*392-1 exactly
    int nc = idx / HALF;
    int q  = idx - nc * HALF;
    int c  = nc & 255;

    float w0 = __ldg(&w[c * 3 + 0]);
    float w1 = __ldg(&w[c * 3 + 1]);
    float w2 = __ldg(&w[c * 3 + 2]);

    const float4* xp = reinterpret_cast<const float4*>(x + (long)nc * THW) + q;
    float4*       yp = reinterpret_cast<float4*>      (y + (long)nc * THW) + q;

    // Two independent streams (q, q+392): compiler builds two rolling
    // windows, doubling outstanding loads per thread.
    float4 xa[T], xb[T];
#pragma unroll
    for (int t = 0; t < T; t++) {
        xa[t] = __ldcs(xp + (long)t * HW4);
        xb[t] = __ldcs(xp + (long)t * HW4 + HALF);
    }

#pragma unroll
    for (int t = 0; t < T; t++) {
        float4 ra, rb;
        ra.x = w1 * xa[t].x;  ra.y = w1 * xa[t].y;
        ra.z = w1 * xa[t].z;  ra.w = w1 * xa[t].w;
        rb.x = w1 * xb[t].x;  rb.y = w1 * xb[t].y;
        rb.z = w1 * xb[t].z;  rb.w = w1 * xb[t].w;
        if (t >= 2) {
            ra.x = fmaf(w0, xa[t-2].x, ra.x);  ra.y = fmaf(w0, xa[t-2].y, ra.y);
            ra.z = fmaf(w0, xa[t-2].z, ra.z);  ra.w = fmaf(w0, xa[t-2].w, ra.w);
            rb.x = fmaf(w0, xb[t-2].x, rb.x);  rb.y = fmaf(w0, xb[t-2].y, rb.y);
            rb.z = fmaf(w0, xb[t-2].z, rb.z);  rb.w = fmaf(w0, xb[t-2].w, rb.w);
        }
        if (t < T - 2) {
            ra.x = fmaf(w2, xa[t+2].x, ra.x);  ra.y = fmaf(w2, xa[t+2].y, ra.y);
            ra.z = fmaf(w2, xa[t+2].z, ra.z);  ra.w = fmaf(w2, xa[t+2].w, ra.w);
            rb.x = fmaf(w2, xb[t+2].x, rb.x);  rb.y = fmaf(w2, xb[t+2].y, rb.y);
            rb.z = fmaf(w2, xb[t+2].z, rb.z);  rb.w = fmaf(w2, xb[t+2].w, rb.w);
        }
        __stcs(yp + (long)t * HW4, ra);
        __stcs(yp + (long)t * HW4 + HALF, rb);
    }
}

extern "C" void kernel_launch(void* const* d_in, const int* in_sizes, int n_in,
                              void* d_out, int out_size)
{
    const float* x = (const float*)d_in[0];
    const float* w = (const float*)d_in[1];
    float* y = (float*)d_out;

    // total threads = 2048 * 392 = 802,816 -> 3136 blocks of 256 (exact)
    constexpr int total   = 2048 * 392;
    constexpr int threads = 256;
    constexpr int blocks  = total / threads;
    tshift_kernel<<<blocks, threads>>>(x, w, y);
}

// round 3
// speedup vs baseline: 1.0369x; 1.0369x over previous
#include <cuda_runtime.h>

// x: [8, 256, 16, 56, 56] fp32, weight: [256, 1, 3] fp32
// y[n,c,t,h,w] = w[c,0]*x[t-2] + w[c,1]*x[t] + w[c,2]*x[t+2]  (zero outside t)
//
// HW = 3136 floats contiguous per (n,c,t); T=16; NC=2048.
// One thread owns one hw4-chunk across the full t-line; compiler builds a
// rolling register window so each input element is read exactly once.
// __launch_bounds__(256, 8) forces <=32 regs -> 8 blocks/SM -> full occupancy.

__global__ __launch_bounds__(256, 8) void tshift_kernel(
    const float* __restrict__ x,
    const float* __restrict__ w,
    float* __restrict__ y)
{
    constexpr int HW4 = 3136 / 4;      // 784 float4 per t-plane
    constexpr int T = 16;
    constexpr int THW = T * 3136;      // floats per (n,c) line

    int idx = blockIdx.x * blockDim.x + threadIdx.x;   // 0 .. 2048*784-1 exactly
    int nc = idx / HW4;
    int q  = idx - nc * HW4;
    int c  = nc & 255;

    float w0 = __ldg(&w[c * 3 + 0]);
    float w1 = __ldg(&w[c * 3 + 1]);
    float w2 = __ldg(&w[c * 3 + 2]);

    const float4* xp = reinterpret_cast<const float4*>(x + (long)nc * THW) + q;
    float4*       yp = reinterpret_cast<float4*>      (y + (long)nc * THW) + q;

    float4 xv[T];
#pragma unroll
    for (int t = 0; t < T; t++)
        xv[t] = xp[(long)t * HW4];

#pragma unroll
    for (int t = 0; t < T; t++) {
        float4 r;
        r.x = w1 * xv[t].x;
        r.y = w1 * xv[t].y;
        r.z = w1 * xv[t].z;
        r.w = w1 * xv[t].w;
        if (t >= 2) {
            r.x = fmaf(w0, xv[t - 2].x, r.x);
            r.y = fmaf(w0, xv[t - 2].y, r.y);
            r.z = fmaf(w0, xv[t - 2].z, r.z);
            r.w = fmaf(w0, xv[t - 2].w, r.w);
        }
        if (t < T - 2) {
            r.x = fmaf(w2, xv[t + 2].x, r.x);
            r.y = fmaf(w2, xv[t + 2].y, r.y);
            r.z = fmaf(w2, xv[t + 2].z, r.z);
            r.w = fmaf(w2, xv[t + 2].w, r.w);
        }
        __stcs(yp + (long)t * HW4, r);
    }
}

extern "C" void kernel_launch(void* const* d_in, const int* in_sizes, int n_in,
                              void* d_out, int out_size)
{
    const float* x = (const float*)d_in[0];
    const float* w = (const float*)d_in[1];
    float* y = (float*)d_out;

    // total threads = 2048 * 784 = 1,605,632 -> 6272 blocks of 256 (exact)
    constexpr int total   = 2048 * 784;
    constexpr int threads = 256;
    constexpr int blocks  = total / threads;
    tshift_kernel<<<blocks, threads>>>(x, w, y);
}

// round 4
// speedup vs baseline: 1.0666x; 1.0286x over previous
#include <cuda_runtime.h>

// x: [8, 256, 16, 56, 56] fp32, weight: [256, 1, 3] fp32
// y[n,c,t,h,w] = w0*x[t-2] + w1*x[t] + w2*x[t+2]  (zero outside t range)
//
// Dilation-2 stencil decouples even and odd t. Each thread owns one
// (nc, parity, hw4-chunk): an 8-plane sub-line with a radius-1 stencil.
// All 8 planes front-batched in registers (MLP=8); each input element is
// read exactly once, each output written exactly once.

__global__ __launch_bounds__(256) void tshift_kernel(
    const float* __restrict__ x,
    const float* __restrict__ w,
    float* __restrict__ y)
{
    constexpr int HW4  = 3136 / 4;     // 784 float4 per t-plane
    constexpr int THW4 = 16 * HW4;     // float4 per (n,c) line
    constexpr int TS   = 8;            // sub-line length (even or odd t)

    int idx = blockIdx.x * blockDim.x + threadIdx.x;  // 0 .. 2048*2*784-1 exactly
    int sub = idx / HW4;               // 0 .. 4095  (nc*2 + parity)
    int q   = idx - sub * HW4;
    int nc  = sub >> 1;
    int par = sub & 1;
    int c   = nc & 255;

    float w0 = __ldg(&w[c * 3 + 0]);
    float w1 = __ldg(&w[c * 3 + 1]);
    float w2 = __ldg(&w[c * 3 + 2]);

    long base = (long)nc * THW4 + (long)par * HW4 + q;
    const float4* xp = reinterpret_cast<const float4*>(x) + base;
    float4*       yp = reinterpret_cast<float4*>(y) + base;

    // Front-batch the whole sub-line: 8 independent LDG.128 in flight.
    float4 xv[TS];
#pragma unroll
    for (int i = 0; i < TS; i++)
        xv[i] = xp[(long)(2 * i) * HW4];

#pragma unroll
    for (int i = 0; i < TS; i++) {
        float4 r;
        r.x = w1 * xv[i].x;
        r.y = w1 * xv[i].y;
        r.z = w1 * xv[i].z;
        r.w = w1 * xv[i].w;
        if (i >= 1) {
            r.x = fmaf(w0, xv[i - 1].x, r.x);
            r.y = fmaf(w0, xv[i - 1].y, r.y);
            r.z = fmaf(w0, xv[i - 1].z, r.z);
            r.w = fmaf(w0, xv[i - 1].w, r.w);
        }
        if (i < TS - 1) {
            r.x = fmaf(w2, xv[i + 1].x, r.x);
            r.y = fmaf(w2, xv[i + 1].y, r.y);
            r.z = fmaf(w2, xv[i + 1].z, r.z);
            r.w = fmaf(w2, xv[i + 1].w, r.w);
        }
        __stcs(yp + (long)(2 * i) * HW4, r);
    }
}

extern "C" void kernel_launch(void* const* d_in, const int* in_sizes, int n_in,
                              void* d_out, int out_size)
{
    const float* x = (const float*)d_in[0];
    const float* w = (const float*)d_in[1];
    float* y = (float*)d_out;

    // total threads = 2048 * 2 * 784 = 3,211,264 -> 12544 blocks of 256 (exact)
    constexpr int total   = 2048 * 2 * 784;
    constexpr int threads = 256;
    constexpr int blocks  = total / threads;
    tshift_kernel<<<blocks, threads>>>(x, w, y);
}

// round 5
// speedup vs baseline: 1.0830x; 1.0153x over previous
#include <cuda_runtime.h>

// x: [8, 256, 16, 56, 56] fp32, weight: [256, 1, 3] fp32
// y[n,c,t,h,w] = w0*x[t-2] + w1*x[t] + w2*x[t+2]  (zero outside t range)
//
// Dilation-2 stencil decouples even and odd t. Each thread owns one
// (nc, parity, hw4-chunk): an 8-plane sub-line with a radius-1 stencil.
// All 8 planes front-batched (MLP=8). Fully streaming access (.cs on both
// loads and stores): zero reuse, so evict-first keeps the read and write
// streams from fighting over L2 residency.

__global__ __launch_bounds__(256) void tshift_kernel(
    const float* __restrict__ x,
    const float* __restrict__ w,
    float* __restrict__ y)
{
    constexpr int HW4  = 3136 / 4;     // 784 float4 per t-plane
    constexpr int THW4 = 16 * HW4;     // float4 per (n,c) line
    constexpr int TS   = 8;            // sub-line length (even or odd t)

    int idx = blockIdx.x * blockDim.x + threadIdx.x;  // 0 .. 2048*2*784-1 exactly
    int sub = idx / HW4;               // 0 .. 4095  (nc*2 + parity)
    int q   = idx - sub * HW4;
    int nc  = sub >> 1;
    int par = sub & 1;
    int c   = nc & 255;

    float w0 = __ldg(&w[c * 3 + 0]);
    float w1 = __ldg(&w[c * 3 + 1]);
    float w2 = __ldg(&w[c * 3 + 2]);

    long base = (long)nc * THW4 + (long)par * HW4 + q;
    const float4* xp = reinterpret_cast<const float4*>(x) + base;
    float4*       yp = reinterpret_cast<float4*>(y) + base;

    // Front-batch the whole sub-line: 8 independent LDG.128.cs in flight.
    float4 xv[TS];
#pragma unroll
    for (int i = 0; i < TS; i++)
        xv[i] = __ldcs(xp + (long)(2 * i) * HW4);

#pragma unroll
    for (int i = 0; i < TS; i++) {
        float4 r;
        r.x = w1 * xv[i].x;
        r.y = w1 * xv[i].y;
        r.z = w1 * xv[i].z;
        r.w = w1 * xv[i].w;
        if (i >= 1) {
            r.x = fmaf(w0, xv[i - 1].x, r.x);
            r.y = fmaf(w0, xv[i - 1].y, r.y);
            r.z = fmaf(w0, xv[i - 1].z, r.z);
            r.w = fmaf(w0, xv[i - 1].w, r.w);
        }
        if (i < TS - 1) {
            r.x = fmaf(w2, xv[i + 1].x, r.x);
            r.y = fmaf(w2, xv[i + 1].y, r.y);
            r.z = fmaf(w2, xv[i + 1].z, r.z);
            r.w = fmaf(w2, xv[i + 1].w, r.w);
        }
        __stcs(yp + (long)(2 * i) * HW4, r);
    }
}

extern "C" void kernel_launch(void* const* d_in, const int* in_sizes, int n_in,
                              void* d_out, int out_size)
{
    const float* x = (const float*)d_in[0];
    const float* w = (const float*)d_in[1];
    float* y = (float*)d_out;

    // total threads = 2048 * 2 * 784 = 3,211,264 -> 12544 blocks of 256 (exact)
    constexpr int total   = 2048 * 2 * 784;
    constexpr int threads = 256;
    constexpr int blocks  = total / threads;
    tshift_kernel<<<blocks, threads>>>(x, w, y);
}